// round 1
// baseline (speedup 1.0000x reference)
#include <cuda_runtime.h>
#include <cstdio>

#define N_NODES 10000
#define N_EDGES 320000
#define IN_DIM  64
#define HID     128
#define G3      384           // 3*HID
#define HEADS1  4
#define HC1     512           // HEADS1*HID
#define OUTD    64
#define TOT_E   (N_EDGES + N_NODES)

// ---------------- scratch (__device__ globals; no allocation allowed) ----------------
__device__ float g_gi  [N_NODES * G3];     // gate input projections (reused by both layers)
__device__ float g_h0  [N_NODES * HID];    // GRU layer0 output
__device__ float g_h1  [N_NODES * HID];    // GRU layer1 output
__device__ float g_hf1 [N_NODES * HC1];    // GAT1 transformed features
__device__ float g_gat1[N_NODES * HC1];    // GAT1 output (post relu)
__device__ float g_hf2 [N_NODES * OUTD];   // GAT2 transformed features
__device__ float g_pas1[N_NODES * HEADS1];
__device__ float g_pad1[N_NODES * HEADS1];
__device__ float g_pas2[N_NODES];
__device__ float g_pad2[N_NODES];
__device__ int   g_deg [N_NODES];
__device__ int   g_off [N_NODES + 1];
__device__ int   g_cur [N_NODES];
__device__ int   g_adj [TOT_E];
__device__ int   g_is64;

// ---------------- helpers ----------------
__device__ __forceinline__ float sigmoidf_(float x) {
    return __fdividef(1.f, 1.f + __expf(-x));
}
__device__ __forceinline__ float tanhf_(float x) {
    return 1.f - __fdividef(2.f, __expf(2.f * x) + 1.f);
}

// ---------------- edge dtype detection (int64 vs int32) ----------------
__global__ void detect_dtype(const unsigned int* __restrict__ e) {
    if (threadIdx.x == 0 && blockIdx.x == 0) {
        int is64 = 1;
        for (int i = 1; i < 256; i += 2)
            if (e[i] != 0u) { is64 = 0; break; }
        g_is64 = is64;
    }
}
__device__ __forceinline__ int ld_edge(const void* e, int i) {
    if (g_is64) return (int)((const long long*)e)[i];
    return ((const int*)e)[i];
}

// ---------------- GEMMs ----------------
// out[n][m] = bias[m] + sum_k A[n][k] * B[m][k]   (B row-major [M,K]) — for gi = x @ W_ih^T
__global__ void gemm_nt(const float* __restrict__ A, const float* __restrict__ B,
                        const float* __restrict__ bias, float* __restrict__ out,
                        int N, int K, int M) {
    int idx = blockIdx.x * blockDim.x + threadIdx.x;
    if (idx >= N * M) return;
    int n = idx / M, m = idx - n * M;
    const float4* a = reinterpret_cast<const float4*>(A + (long)n * K);
    const float4* b = reinterpret_cast<const float4*>(B + (long)m * K);
    float acc = 0.f;
    int K4 = K >> 2;
    for (int k = 0; k < K4; ++k) {
        float4 av = a[k], bv = b[k];
        acc += av.x * bv.x; acc += av.y * bv.y;
        acc += av.z * bv.z; acc += av.w * bv.w;
    }
    out[idx] = acc + bias[m];
}

// out[n][m] = sum_k A[n][k] * B[k][m]   (B row-major [K,M]) — for feature transforms
__global__ void gemm_nn(const float* __restrict__ A, const float* __restrict__ B,
                        float* __restrict__ out, int N, int K, int M) {
    int M4 = M >> 2;
    int idx = blockIdx.x * blockDim.x + threadIdx.x;
    if (idx >= N * M4) return;
    int n = idx / M4, m4 = idx - n * M4;
    const float* arow = A + (long)n * K;
    const float4* bp = reinterpret_cast<const float4*>(B) + m4;
    float4 acc = make_float4(0.f, 0.f, 0.f, 0.f);
    for (int k = 0; k < K; ++k) {
        float av = arow[k];
        float4 bv = bp[(long)k * M4];
        acc.x += av * bv.x; acc.y += av * bv.y;
        acc.z += av * bv.z; acc.w += av * bv.w;
    }
    reinterpret_cast<float4*>(out)[idx] = acc;
}

// ---------------- GRU sequential scan: 1 block, 384 threads ----------------
// thread t owns row t of w_hh (3H x H) in 64 packed f32x2 registers.
__global__ void __launch_bounds__(384, 1)
gru_scan(const float* __restrict__ gi,    // [T, 384]
         const float* __restrict__ w_hh,  // [384, 128]
         const float* __restrict__ b_hh,  // [384]
         float* __restrict__ out,         // [T, 128]
         int T) {
    __shared__ __align__(16) unsigned long long hs[64];  // h packed as 64 f32x2
    __shared__ float sgh[384];
    __shared__ float sgin[128];

    const int t = threadIdx.x;

    unsigned long long w[64];
    const float2* wrow = reinterpret_cast<const float2*>(w_hh + t * 128);
#pragma unroll
    for (int k = 0; k < 64; ++k) {
        float2 v = wrow[k];
        unsigned long long u;
        asm("mov.b64 %0, {%1, %2};" : "=l"(u) : "f"(v.x), "f"(v.y));
        w[k] = u;
    }
    float bh = b_hh[t];
    if (t < 64) hs[t] = 0ull;
    __syncthreads();

    for (int step = 0; step < T; ++step) {
        float giv = gi[step * 384 + t];  // issue early; consumed post-dot
        unsigned long long a0 = 0ull, a1 = 0ull, a2 = 0ull, a3 = 0ull;
#pragma unroll
        for (int k = 0; k < 64; k += 4) {
            ulonglong2 h01 = *reinterpret_cast<const ulonglong2*>(&hs[k]);
            ulonglong2 h23 = *reinterpret_cast<const ulonglong2*>(&hs[k + 2]);
            asm("fma.rn.f32x2 %0, %1, %2, %0;" : "+l"(a0) : "l"(w[k]),     "l"(h01.x));
            asm("fma.rn.f32x2 %0, %1, %2, %0;" : "+l"(a1) : "l"(w[k + 1]), "l"(h01.y));
            asm("fma.rn.f32x2 %0, %1, %2, %0;" : "+l"(a2) : "l"(w[k + 2]), "l"(h23.x));
            asm("fma.rn.f32x2 %0, %1, %2, %0;" : "+l"(a3) : "l"(w[k + 3]), "l"(h23.y));
        }
        asm("add.rn.f32x2 %0, %0, %1;" : "+l"(a0) : "l"(a1));
        asm("add.rn.f32x2 %0, %0, %1;" : "+l"(a2) : "l"(a3));
        asm("add.rn.f32x2 %0, %0, %1;" : "+l"(a0) : "l"(a2));
        float lo, hi;
        asm("mov.b64 {%0, %1}, %2;" : "=f"(lo), "=f"(hi) : "l"(a0));
        float gh = lo + hi + bh;

        sgh[t] = (t < 256) ? (gh + giv) : gh;
        if (t >= 256) sgin[t - 256] = giv;
        __syncthreads();

        if (t < 128) {
            float r = sigmoidf_(sgh[t]);
            float z = sigmoidf_(sgh[t + 128]);
            float n = tanhf_(sgin[t] + r * sgh[t + 256]);
            float hold = reinterpret_cast<const float*>(hs)[t];
            float hnew = (1.f - z) * n + z * hold;
            reinterpret_cast<float*>(hs)[t] = hnew;
            out[step * 128 + t] = hnew;
        }
        __syncthreads();
    }
}

// ---------------- CSR build (by destination, self loops included) ----------------
__global__ void init_deg() {
    int n = blockIdx.x * blockDim.x + threadIdx.x;
    if (n < N_NODES) g_deg[n] = 1;  // self loop
}
__global__ void count_deg(const void* e) {
    int i = blockIdx.x * blockDim.x + threadIdx.x;
    if (i < N_EDGES) {
        int dst = ld_edge(e, N_EDGES + i);
        atomicAdd(&g_deg[dst], 1);
    }
}
__global__ void exscan_k() {
    __shared__ int part[1024];
    const int CH = 10;  // 1024*10 >= 10000
    int tid = threadIdx.x;
    int base = tid * CH;
    int s = 0;
    for (int i = 0; i < CH; ++i) {
        int idx = base + i;
        if (idx < N_NODES) s += g_deg[idx];
    }
    part[tid] = s;
    __syncthreads();
    if (tid == 0) {
        int run = 0;
        for (int i = 0; i < 1024; ++i) { int v = part[i]; part[i] = run; run += v; }
        g_off[N_NODES] = run;
    }
    __syncthreads();
    int run = part[tid];
    for (int i = 0; i < CH; ++i) {
        int idx = base + i;
        if (idx < N_NODES) {
            g_off[idx] = run;
            g_cur[idx] = run;
            run += g_deg[idx];
        }
    }
}
__global__ void fill_edges(const void* e) {
    int i = blockIdx.x * blockDim.x + threadIdx.x;
    if (i < N_EDGES) {
        int src = ld_edge(e, i);
        int dst = ld_edge(e, N_EDGES + i);
        int p = atomicAdd(&g_cur[dst], 1);
        g_adj[p] = src;
    }
}
__global__ void fill_self() {
    int n = blockIdx.x * blockDim.x + threadIdx.x;
    if (n < N_NODES) {
        int p = atomicAdd(&g_cur[n], 1);
        g_adj[p] = n;
    }
}

// ---------------- attention dot products ----------------
template <int HEADS, int C>
__global__ void att_dots(const float* __restrict__ hf, const float* __restrict__ atts,
                         const float* __restrict__ attd,
                         float* __restrict__ a_s, float* __restrict__ a_d) {
    int idx = blockIdx.x * blockDim.x + threadIdx.x;
    if (idx >= N_NODES * HEADS) return;
    int n = idx / HEADS, h = idx - n * HEADS;
    const float* v = hf + (long)n * HEADS * C + h * C;
    float s = 0.f, d = 0.f;
#pragma unroll 4
    for (int c = 0; c < C; ++c) {
        float xv = v[c];
        s += xv * atts[h * C + c];
        d += xv * attd[h * C + c];
    }
    a_s[idx] = s;
    a_d[idx] = d;
}

// ---------------- GAT aggregation: one warp per destination node ----------------
template <int HEADS, int C, bool RELU>
__global__ void gat_aggregate(const float* __restrict__ hf, const float* __restrict__ a_s,
                              const float* __restrict__ a_d, const float* __restrict__ bias,
                              float* __restrict__ out) {
    constexpr int HC  = HEADS * C;
    constexpr int FPL = HC / 32;
    int warp = (blockIdx.x * blockDim.x + threadIdx.x) >> 5;
    int lane = threadIdx.x & 31;
    if (warp >= N_NODES) return;
    int s0 = g_off[warp], s1 = g_off[warp + 1];

    float ad[HEADS], m[HEADS], den[HEADS];
#pragma unroll
    for (int h = 0; h < HEADS; ++h) {
        ad[h] = a_d[warp * HEADS + h];
        m[h] = -1e30f;
        den[h] = 0.f;
    }
    // pass 1: segment max of leaky_relu(a_s[src] + a_d[dst])
    for (int j = s0 + lane; j < s1; j += 32) {
        int src = g_adj[j];
#pragma unroll
        for (int h = 0; h < HEADS; ++h) {
            float e = a_s[src * HEADS + h] + ad[h];
            e = (e > 0.f) ? e : 0.2f * e;
            m[h] = fmaxf(m[h], e);
        }
    }
#pragma unroll
    for (int h = 0; h < HEADS; ++h)
        for (int o = 16; o > 0; o >>= 1)
            m[h] = fmaxf(m[h], __shfl_xor_sync(0xffffffffu, m[h], o));
    // pass 2: softmax denominator
    for (int j = s0 + lane; j < s1; j += 32) {
        int src = g_adj[j];
#pragma unroll
        for (int h = 0; h < HEADS; ++h) {
            float e = a_s[src * HEADS + h] + ad[h];
            e = (e > 0.f) ? e : 0.2f * e;
            den[h] += __expf(e - m[h]);
        }
    }
#pragma unroll
    for (int h = 0; h < HEADS; ++h) {
        for (int o = 16; o > 0; o >>= 1)
            den[h] += __shfl_xor_sync(0xffffffffu, den[h], o);
        den[h] = __fdividef(1.f, den[h]);
    }
    // pass 3: weighted aggregation, accumulators in registers
    float acc[FPL];
#pragma unroll
    for (int f = 0; f < FPL; ++f) acc[f] = 0.f;
    for (int j = s0; j < s1; ++j) {
        int src = g_adj[j];
        float w[HEADS];
#pragma unroll
        for (int h = 0; h < HEADS; ++h) {
            float e = a_s[src * HEADS + h] + ad[h];
            e = (e > 0.f) ? e : 0.2f * e;
            w[h] = __expf(e - m[h]) * den[h];
        }
        const float* hrow = hf + (long)src * HC;
#pragma unroll
        for (int f = 0; f < FPL; ++f)
            acc[f] += w[(f * 32) / C] * hrow[lane + f * 32];
    }
#pragma unroll
    for (int f = 0; f < FPL; ++f) {
        int feat = lane + f * 32;
        float v = acc[f] + bias[feat];
        if (RELU) v = fmaxf(v, 0.f);
        out[(long)warp * HC + feat] = v;
    }
}

// ---------------- launch ----------------
extern "C" void kernel_launch(void* const* d_in, const int* in_sizes, int n_in,
                              void* d_out, int out_size) {
    const float* x     = (const float*)d_in[0];
    const void*  eix   = d_in[1];
    const float* w_ih0 = (const float*)d_in[2];
    const float* w_hh0 = (const float*)d_in[3];
    const float* b_ih0 = (const float*)d_in[4];
    const float* b_hh0 = (const float*)d_in[5];
    const float* w_ih1 = (const float*)d_in[6];
    const float* w_hh1 = (const float*)d_in[7];
    const float* b_ih1 = (const float*)d_in[8];
    const float* b_hh1 = (const float*)d_in[9];
    const float* W1    = (const float*)d_in[10];
    const float* as1   = (const float*)d_in[11];
    const float* ad1   = (const float*)d_in[12];
    const float* bias1 = (const float*)d_in[13];
    const float* W2    = (const float*)d_in[14];
    const float* as2   = (const float*)d_in[15];
    const float* ad2   = (const float*)d_in[16];
    const float* bias2 = (const float*)d_in[17];
    float* out = (float*)d_out;

    float *gi, *h0, *h1, *hf1, *gat1, *hf2, *pas1, *pad1, *pas2, *pad2;
    cudaGetSymbolAddress((void**)&gi,   g_gi);
    cudaGetSymbolAddress((void**)&h0,   g_h0);
    cudaGetSymbolAddress((void**)&h1,   g_h1);
    cudaGetSymbolAddress((void**)&hf1,  g_hf1);
    cudaGetSymbolAddress((void**)&gat1, g_gat1);
    cudaGetSymbolAddress((void**)&hf2,  g_hf2);
    cudaGetSymbolAddress((void**)&pas1, g_pas1);
    cudaGetSymbolAddress((void**)&pad1, g_pad1);
    cudaGetSymbolAddress((void**)&pas2, g_pas2);
    cudaGetSymbolAddress((void**)&pad2, g_pad2);

    detect_dtype<<<1, 32>>>((const unsigned int*)eix);

    // GRU layer 0
    gemm_nt<<<(N_NODES * G3 + 255) / 256, 256>>>(x, w_ih0, b_ih0, gi, N_NODES, IN_DIM, G3);
    gru_scan<<<1, 384>>>(gi, w_hh0, b_hh0, h0, N_NODES);
    // GRU layer 1
    gemm_nt<<<(N_NODES * G3 + 255) / 256, 256>>>(h0, w_ih1, b_ih1, gi, N_NODES, HID, G3);
    gru_scan<<<1, 384>>>(gi, w_hh1, b_hh1, h1, N_NODES);

    // CSR build (dst-indexed, with self loops)
    init_deg<<<(N_NODES + 255) / 256, 256>>>();
    count_deg<<<(N_EDGES + 255) / 256, 256>>>(eix);
    exscan_k<<<1, 1024>>>();
    fill_edges<<<(N_EDGES + 255) / 256, 256>>>(eix);
    fill_self<<<(N_NODES + 255) / 256, 256>>>();

    // GAT layer 1 (4 heads, C=128, concat) + relu
    gemm_nn<<<(N_NODES * (HC1 / 4) + 255) / 256, 256>>>(h1, W1, hf1, N_NODES, HID, HC1);
    att_dots<HEADS1, HID><<<(N_NODES * HEADS1 + 255) / 256, 256>>>(hf1, as1, ad1, pas1, pad1);
    gat_aggregate<HEADS1, HID, true><<<(N_NODES * 32 + 255) / 256, 256>>>(hf1, pas1, pad1, bias1, gat1);

    // GAT layer 2 (1 head, C=64)
    gemm_nn<<<(N_NODES * (OUTD / 4) + 255) / 256, 256>>>(gat1, W2, hf2, N_NODES, HC1, OUTD);
    att_dots<1, OUTD><<<(N_NODES + 255) / 256, 256>>>(hf2, as2, ad2, pas2, pad2);
    gat_aggregate<1, OUTD, false><<<(N_NODES * 32 + 255) / 256, 256>>>(hf2, pas2, pad2, bias2, out);
}

// round 2
// speedup vs baseline: 1.9062x; 1.9062x over previous
#include <cuda_runtime.h>

#define N_NODES 10000
#define N_EDGES 320000
#define IN_DIM  64
#define HID     128
#define G3      384
#define HEADS1  4
#define HC1     512
#define OUTD    64
#define TOT_E   (N_EDGES + N_NODES)

#define SL      64                       // rows per pipeline slice
#define NS      ((N_NODES + SL - 1) / SL) // 157 slices
#define GA      32                       // gi0 GEMM CTAs
#define GB      32                       // gi1 GEMM CTAs
#define GD      40                       // hf1 GEMM CTAs
#define MEGA_BLOCKS (2 + GA + GB + GD)   // 106

typedef unsigned long long ull;

// ---------------- scratch ----------------
__device__ __align__(16) float g_gi0 [N_NODES * G3];
__device__ __align__(16) float g_gi1 [N_NODES * G3];
__device__ __align__(16) float g_h0  [N_NODES * HID];
__device__ __align__(16) float g_h1  [N_NODES * HID];
__device__ __align__(16) float g_hf1 [N_NODES * HC1];
__device__ __align__(16) float g_gat1[N_NODES * HC1];
__device__ __align__(16) float g_hf2 [N_NODES * OUTD];
__device__ float g_pas1[N_NODES * HEADS1];
__device__ float g_pad1[N_NODES * HEADS1];
__device__ float g_pas2[N_NODES];
__device__ float g_pad2[N_NODES];
__device__ int   g_deg [N_NODES];
__device__ int   g_off [N_NODES + 1];
__device__ int   g_cur [N_NODES];
__device__ int   g_adj [TOT_E];
__device__ int   g_is64;
// pipeline sync
__device__ int   g_f0[NS];     // gi0 slice ready flags
__device__ int   g_f1[NS];     // gi1 slice ready flags
__device__ int   g_h0done;     // h0 rows complete
__device__ int   g_h1done;     // h1 rows complete

__global__ void reset_flags() {
    int i = threadIdx.x;
    for (int s = i; s < NS; s += blockDim.x) { g_f0[s] = 0; g_f1[s] = 0; }
    if (i == 0) { g_h0done = 0; g_h1done = 0; }
}

// ---------------- helpers ----------------
__device__ __forceinline__ float sigmoidf_(float x) {
    return __fdividef(1.f, 1.f + __expf(-x));
}
__device__ __forceinline__ float tanhf_(float x) {
    return 1.f - __fdividef(2.f, __expf(2.f * x) + 1.f);
}
__device__ __forceinline__ ull packf2(float x, float y) {
    ull u; asm("mov.b64 %0, {%1, %2};" : "=l"(u) : "f"(x), "f"(y)); return u;
}
__device__ __forceinline__ void unpackf2(ull u, float& x, float& y) {
    asm("mov.b64 {%0, %1}, %2;" : "=f"(x), "=f"(y) : "l"(u));
}

// ---------------- edge dtype detection ----------------
__global__ void detect_dtype(const unsigned int* __restrict__ e) {
    if (threadIdx.x == 0 && blockIdx.x == 0) {
        int is64 = 1;
        for (int i = 1; i < 256; i += 2)
            if (e[i] != 0u) { is64 = 0; break; }
        g_is64 = is64;
    }
}
__device__ __forceinline__ int ld_edge(const void* e, int i) {
    if (g_is64) return (int)((const long long*)e)[i];
    return ((const int*)e)[i];
}

// =========================================================================
// MEGA KERNEL roles
// =========================================================================

// ---- GRU scan: 1 CTA, 384 threads; thread t owns row t of w_hh in regs ----
__device__ void scan_role(unsigned char* sraw,
                          const float* __restrict__ gi,
                          const float* __restrict__ w_hh,
                          const float* __restrict__ b_hh,
                          float* __restrict__ out,
                          volatile int* flags, volatile int* prog) {
    ull*   hs   = (ull*)sraw;              // 64 f32x2
    float* sgh  = (float*)(sraw + 512);    // 384
    float* sgin = (float*)(sraw + 2048);   // 128
    const int t = threadIdx.x;

    ull w[64];
    const float2* wrow = reinterpret_cast<const float2*>(w_hh + t * 128);
#pragma unroll
    for (int k = 0; k < 64; ++k) { float2 v = wrow[k]; w[k] = packf2(v.x, v.y); }
    float bh = b_hh[t];
    if (t < 64) hs[t] = 0ull;
    __syncthreads();

    for (int step = 0; step < N_NODES; ++step) {
        if ((step & (SL - 1)) == 0) {               // wait for gi slice
            if (t == 0) { while (flags[step >> 6] == 0) __nanosleep(128); }
            __syncthreads();
            __threadfence();
        }
        float giv = gi[step * G3 + t];
        ull a0 = 0ull, a1 = 0ull, a2 = 0ull, a3 = 0ull;
#pragma unroll
        for (int k = 0; k < 64; k += 4) {
            ulonglong2 h01 = *reinterpret_cast<const ulonglong2*>(&hs[k]);
            ulonglong2 h23 = *reinterpret_cast<const ulonglong2*>(&hs[k + 2]);
            asm("fma.rn.f32x2 %0, %1, %2, %0;" : "+l"(a0) : "l"(w[k]),     "l"(h01.x));
            asm("fma.rn.f32x2 %0, %1, %2, %0;" : "+l"(a1) : "l"(w[k + 1]), "l"(h01.y));
            asm("fma.rn.f32x2 %0, %1, %2, %0;" : "+l"(a2) : "l"(w[k + 2]), "l"(h23.x));
            asm("fma.rn.f32x2 %0, %1, %2, %0;" : "+l"(a3) : "l"(w[k + 3]), "l"(h23.y));
        }
        asm("add.rn.f32x2 %0, %0, %1;" : "+l"(a0) : "l"(a1));
        asm("add.rn.f32x2 %0, %0, %1;" : "+l"(a2) : "l"(a3));
        asm("add.rn.f32x2 %0, %0, %1;" : "+l"(a0) : "l"(a2));
        float lo, hi; unpackf2(a0, lo, hi);
        float gh = lo + hi + bh;

        sgh[t] = (t < 256) ? (gh + giv) : gh;
        if (t >= 256) sgin[t - 256] = giv;
        __syncthreads();

        if (t < 128) {
            float r = sigmoidf_(sgh[t]);
            float z = sigmoidf_(sgh[t + 128]);
            float n = tanhf_(sgin[t] + r * sgh[t + 256]);
            float hold = reinterpret_cast<const float*>(hs)[t];
            float hnew = (1.f - z) * n + z * hold;
            reinterpret_cast<float*>(hs)[t] = hnew;
            out[step * HID + t] = hnew;
        }
        __syncthreads();

        if ((step & 15) == 15 || step == N_NODES - 1) {  // publish progress
            __threadfence();
            __syncthreads();
            if (t == 0) *prog = step + 1;
        }
    }
}

// ---- gi0 = x @ w_ih0^T + b_ih0 : slices round-robin ----
__device__ void gemmA_role(unsigned char* sraw, int cta,
                           const float* __restrict__ x,
                           const float* __restrict__ w_ih,
                           const float* __restrict__ b_ih) {
    float* sx = (float*)sraw;  // 64x64 slice of x (16KB)
    const int t = threadIdx.x;
    float4 w[16];
    const float4* wr = reinterpret_cast<const float4*>(w_ih + t * IN_DIM);
#pragma unroll
    for (int i = 0; i < 16; ++i) w[i] = wr[i];
    float b = b_ih[t];

    for (int s = cta; s < NS; s += GA) {
        int r0 = s * SL, r1 = min(r0 + SL, N_NODES), nr = r1 - r0;
        for (int i = t; i < nr * IN_DIM; i += 384) sx[i] = x[r0 * IN_DIM + i];
        __syncthreads();
        for (int r = 0; r < nr; ++r) {
            const float4* hx = reinterpret_cast<const float4*>(sx + r * IN_DIM);
            float acc = b;
#pragma unroll
            for (int i = 0; i < 16; ++i) {
                float4 a = hx[i];
                acc += a.x * w[i].x + a.y * w[i].y + a.z * w[i].z + a.w * w[i].w;
            }
            g_gi0[(r0 + r) * G3 + t] = acc;
        }
        __threadfence();
        __syncthreads();
        if (t == 0) ((volatile int*)g_f0)[s] = 1;
        __syncthreads();
    }
}

// ---- gi1 = h0 @ w_ih1^T + b_ih1 : polls h0 progress ----
__device__ void gemmB_role(unsigned char* sraw, int cta,
                           const float* __restrict__ w_ih,
                           const float* __restrict__ b_ih) {
    ull* sh = (ull*)sraw;  // 64 rows x 64 f32x2 (32KB)
    const int t = threadIdx.x;
    ull w[64];
    const float2* wr = reinterpret_cast<const float2*>(w_ih + t * HID);
#pragma unroll
    for (int k = 0; k < 64; ++k) { float2 v = wr[k]; w[k] = packf2(v.x, v.y); }
    float b = b_ih[t];

    for (int s = cta; s < NS; s += GB) {
        int r0 = s * SL, r1 = min(r0 + SL, N_NODES), nr = r1 - r0;
        if (t == 0) { while (*(volatile int*)&g_h0done < r1) __nanosleep(256); }
        __syncthreads();
        __threadfence();
        const ull* src = reinterpret_cast<const ull*>(g_h0 + r0 * HID);
        for (int i = t; i < nr * 64; i += 384) sh[i] = src[i];
        __syncthreads();
        for (int r = 0; r < nr; ++r) {
            const ull* hr = sh + r * 64;
            ull a0 = 0ull, a1 = 0ull;
#pragma unroll
            for (int k = 0; k < 64; k += 2) {
                asm("fma.rn.f32x2 %0, %1, %2, %0;" : "+l"(a0) : "l"(w[k]),     "l"(hr[k]));
                asm("fma.rn.f32x2 %0, %1, %2, %0;" : "+l"(a1) : "l"(w[k + 1]), "l"(hr[k + 1]));
            }
            asm("add.rn.f32x2 %0, %0, %1;" : "+l"(a0) : "l"(a1));
            float lo, hi; unpackf2(a0, lo, hi);
            g_gi1[(r0 + r) * G3 + t] = lo + hi + b;
        }
        __threadfence();
        __syncthreads();
        if (t == 0) ((volatile int*)g_f1)[s] = 1;
        __syncthreads();
    }
}

// ---- hf1 = h1 @ W1 (+ attention dots) : polls h1 progress ----
__device__ void gemmD_role(unsigned char* sraw, int cta,
                           const float* __restrict__ W1,
                           const float* __restrict__ as1,
                           const float* __restrict__ ad1) {
    ull* sh = (ull*)sraw;  // h1 slice, 64 rows x 64 f32x2
    const int t = threadIdx.x;

    for (int s = cta; s < NS; s += GD) {
        int r0 = s * SL, r1 = min(r0 + SL, N_NODES), nr = r1 - r0;
        if (t == 0) { while (*(volatile int*)&g_h1done < r1) __nanosleep(256); }
        __syncthreads();
        __threadfence();
        const ull* src = reinterpret_cast<const ull*>(g_h1 + r0 * HID);
        for (int i = t; i < nr * 64; i += 384) sh[i] = src[i];
        __syncthreads();

        // pass A: columns 0..383 (thread t -> column t)
        {
            int col = t;
            ull w[64];
#pragma unroll
            for (int k = 0; k < 64; ++k)
                w[k] = packf2(W1[(2 * k) * HC1 + col], W1[(2 * k + 1) * HC1 + col]);
            for (int r = 0; r < nr; ++r) {
                const ull* hr = sh + r * 64;
                ull a0 = 0ull, a1 = 0ull;
#pragma unroll
                for (int k = 0; k < 64; k += 2) {
                    asm("fma.rn.f32x2 %0, %1, %2, %0;" : "+l"(a0) : "l"(w[k]),     "l"(hr[k]));
                    asm("fma.rn.f32x2 %0, %1, %2, %0;" : "+l"(a1) : "l"(w[k + 1]), "l"(hr[k + 1]));
                }
                asm("add.rn.f32x2 %0, %0, %1;" : "+l"(a0) : "l"(a1));
                float lo, hi; unpackf2(a0, lo, hi);
                g_hf1[(long)(r0 + r) * HC1 + col] = lo + hi;
            }
        }
        // pass B: columns 384..511 (threads 0..127)
        if (t < 128) {
            int col = 384 + t;
            ull w[64];
#pragma unroll
            for (int k = 0; k < 64; ++k)
                w[k] = packf2(W1[(2 * k) * HC1 + col], W1[(2 * k + 1) * HC1 + col]);
            for (int r = 0; r < nr; ++r) {
                const ull* hr = sh + r * 64;
                ull a0 = 0ull, a1 = 0ull;
#pragma unroll
                for (int k = 0; k < 64; k += 2) {
                    asm("fma.rn.f32x2 %0, %1, %2, %0;" : "+l"(a0) : "l"(w[k]),     "l"(hr[k]));
                    asm("fma.rn.f32x2 %0, %1, %2, %0;" : "+l"(a1) : "l"(w[k + 1]), "l"(hr[k + 1]));
                }
                asm("add.rn.f32x2 %0, %0, %1;" : "+l"(a0) : "l"(a1));
                float lo, hi; unpackf2(a0, lo, hi);
                g_hf1[(long)(r0 + r) * HC1 + col] = lo + hi;
            }
        }
        __syncthreads();

        // attention dots for this slice: 256 threads = 64 rows x 4 heads
        if (t < 256) {
            int row = t >> 2, h = t & 3;
            if (row < nr) {
                const float* v = g_hf1 + (long)(r0 + row) * HC1 + h * HID;
                float sa = 0.f, da = 0.f;
#pragma unroll 4
                for (int c = 0; c < HID; ++c) {
                    float xv = v[c];
                    sa += xv * as1[h * HID + c];
                    da += xv * ad1[h * HID + c];
                }
                g_pas1[(r0 + row) * HEADS1 + h] = sa;
                g_pad1[(r0 + row) * HEADS1 + h] = da;
            }
        }
        __syncthreads();
    }
}

__global__ void __launch_bounds__(384, 1)
mega(const float* __restrict__ x,
     const float* __restrict__ w_ih0, const float* __restrict__ b_ih0,
     const float* __restrict__ w_hh0, const float* __restrict__ b_hh0,
     const float* __restrict__ w_ih1, const float* __restrict__ b_ih1,
     const float* __restrict__ w_hh1, const float* __restrict__ b_hh1,
     const float* __restrict__ W1,
     const float* __restrict__ as1, const float* __restrict__ ad1) {
    __shared__ __align__(16) unsigned char sraw[64 * 64 * 8];  // 32KB, role-shared
    int b = blockIdx.x;
    if (b == 0)
        scan_role(sraw, g_gi0, w_hh0, b_hh0, g_h0, (volatile int*)g_f0, (volatile int*)&g_h0done);
    else if (b == 1)
        scan_role(sraw, g_gi1, w_hh1, b_hh1, g_h1, (volatile int*)g_f1, (volatile int*)&g_h1done);
    else if (b < 2 + GA)
        gemmA_role(sraw, b - 2, x, w_ih0, b_ih0);
    else if (b < 2 + GA + GB)
        gemmB_role(sraw, b - 2 - GA, w_ih1, b_ih1);
    else
        gemmD_role(sraw, b - 2 - GA - GB, W1, as1, ad1);
}

// =========================================================================
// CSR build (by destination, self loops included)
// =========================================================================
__global__ void init_deg() {
    int n = blockIdx.x * blockDim.x + threadIdx.x;
    if (n < N_NODES) g_deg[n] = 1;
}
__global__ void count_deg(const void* e) {
    int i = blockIdx.x * blockDim.x + threadIdx.x;
    if (i < N_EDGES) atomicAdd(&g_deg[ld_edge(e, N_EDGES + i)], 1);
}
__global__ void exscan_k() {
    __shared__ int part[1024];
    const int CH = 10;
    int tid = threadIdx.x;
    int base = tid * CH;
    int s = 0;
    for (int i = 0; i < CH; ++i) { int idx = base + i; if (idx < N_NODES) s += g_deg[idx]; }
    part[tid] = s;
    __syncthreads();
    if (tid == 0) {
        int run = 0;
        for (int i = 0; i < 1024; ++i) { int v = part[i]; part[i] = run; run += v; }
        g_off[N_NODES] = run;
    }
    __syncthreads();
    int run = part[tid];
    for (int i = 0; i < CH; ++i) {
        int idx = base + i;
        if (idx < N_NODES) { g_off[idx] = run; g_cur[idx] = run; run += g_deg[idx]; }
    }
}
__global__ void fill_edges(const void* e) {
    int i = blockIdx.x * blockDim.x + threadIdx.x;
    if (i < N_EDGES) {
        int src = ld_edge(e, i);
        int dst = ld_edge(e, N_EDGES + i);
        g_adj[atomicAdd(&g_cur[dst], 1)] = src;
    }
}
__global__ void fill_self() {
    int n = blockIdx.x * blockDim.x + threadIdx.x;
    if (n < N_NODES) g_adj[atomicAdd(&g_cur[n], 1)] = n;
}

// =========================================================================
// tail kernels
// =========================================================================
template <int HEADS, int C>
__global__ void att_dots(const float* __restrict__ hf, const float* __restrict__ atts,
                         const float* __restrict__ attd,
                         float* __restrict__ a_s, float* __restrict__ a_d) {
    int idx = blockIdx.x * blockDim.x + threadIdx.x;
    if (idx >= N_NODES * HEADS) return;
    int n = idx / HEADS, h = idx - n * HEADS;
    const float* v = hf + (long)n * HEADS * C + h * C;
    float s = 0.f, d = 0.f;
#pragma unroll 4
    for (int c = 0; c < C; ++c) {
        float xv = v[c];
        s += xv * atts[h * C + c];
        d += xv * attd[h * C + c];
    }
    a_s[idx] = s;
    a_d[idx] = d;
}

template <int HEADS, int C, bool RELU>
__global__ void gat_aggregate(const float* __restrict__ hf, const float* __restrict__ a_s,
                              const float* __restrict__ a_d, const float* __restrict__ bias,
                              float* __restrict__ out) {
    constexpr int HC  = HEADS * C;
    constexpr int FPL = HC / 32;
    int warp = (blockIdx.x * blockDim.x + threadIdx.x) >> 5;
    int lane = threadIdx.x & 31;
    if (warp >= N_NODES) return;
    int s0 = g_off[warp], s1 = g_off[warp + 1];

    float ad[HEADS], m[HEADS], den[HEADS];
#pragma unroll
    for (int h = 0; h < HEADS; ++h) {
        ad[h] = a_d[warp * HEADS + h];
        m[h] = -1e30f;
        den[h] = 0.f;
    }
    for (int j = s0 + lane; j < s1; j += 32) {
        int src = g_adj[j];
#pragma unroll
        for (int h = 0; h < HEADS; ++h) {
            float e = a_s[src * HEADS + h] + ad[h];
            e = (e > 0.f) ? e : 0.2f * e;
            m[h] = fmaxf(m[h], e);
        }
    }
#pragma unroll
    for (int h = 0; h < HEADS; ++h)
        for (int o = 16; o > 0; o >>= 1)
            m[h] = fmaxf(m[h], __shfl_xor_sync(0xffffffffu, m[h], o));
    for (int j = s0 + lane; j < s1; j += 32) {
        int src = g_adj[j];
#pragma unroll
        for (int h = 0; h < HEADS; ++h) {
            float e = a_s[src * HEADS + h] + ad[h];
            e = (e > 0.f) ? e : 0.2f * e;
            den[h] += __expf(e - m[h]);
        }
    }
#pragma unroll
    for (int h = 0; h < HEADS; ++h) {
        for (int o = 16; o > 0; o >>= 1)
            den[h] += __shfl_xor_sync(0xffffffffu, den[h], o);
        den[h] = __fdividef(1.f, den[h]);
    }
    float acc[FPL];
#pragma unroll
    for (int f = 0; f < FPL; ++f) acc[f] = 0.f;
    for (int j = s0; j < s1; ++j) {
        int src = g_adj[j];
        float w[HEADS];
#pragma unroll
        for (int h = 0; h < HEADS; ++h) {
            float e = a_s[src * HEADS + h] + ad[h];
            e = (e > 0.f) ? e : 0.2f * e;
            w[h] = __expf(e - m[h]) * den[h];
        }
        const float* hrow = hf + (long)src * HC;
#pragma unroll
        for (int f = 0; f < FPL; ++f)
            acc[f] += w[(f * 32) / C] * hrow[lane + f * 32];
    }
#pragma unroll
    for (int f = 0; f < FPL; ++f) {
        int feat = lane + f * 32;
        float v = acc[f] + bias[feat];
        if (RELU) v = fmaxf(v, 0.f);
        out[(long)warp * HC + feat] = v;
    }
}

// out[n][m] = sum_k A[n][k]*B[k][m]
__global__ void gemm_nn(const float* __restrict__ A, const float* __restrict__ B,
                        float* __restrict__ out, int N, int K, int M) {
    int M4 = M >> 2;
    int idx = blockIdx.x * blockDim.x + threadIdx.x;
    if (idx >= N * M4) return;
    int n = idx / M4, m4 = idx - n * M4;
    const float* arow = A + (long)n * K;
    const float4* bp = reinterpret_cast<const float4*>(B) + m4;
    float4 acc = make_float4(0.f, 0.f, 0.f, 0.f);
    for (int k = 0; k < K; ++k) {
        float av = arow[k];
        float4 bv = bp[(long)k * M4];
        acc.x += av * bv.x; acc.y += av * bv.y;
        acc.z += av * bv.z; acc.w += av * bv.w;
    }
    reinterpret_cast<float4*>(out)[idx] = acc;
}

// =========================================================================
// launch
// =========================================================================
extern "C" void kernel_launch(void* const* d_in, const int* in_sizes, int n_in,
                              void* d_out, int out_size) {
    const float* x     = (const float*)d_in[0];
    const void*  eix   = d_in[1];
    const float* w_ih0 = (const float*)d_in[2];
    const float* w_hh0 = (const float*)d_in[3];
    const float* b_ih0 = (const float*)d_in[4];
    const float* b_hh0 = (const float*)d_in[5];
    const float* w_ih1 = (const float*)d_in[6];
    const float* w_hh1 = (const float*)d_in[7];
    const float* b_ih1 = (const float*)d_in[8];
    const float* b_hh1 = (const float*)d_in[9];
    const float* W1    = (const float*)d_in[10];
    const float* as1   = (const float*)d_in[11];
    const float* ad1   = (const float*)d_in[12];
    const float* bias1 = (const float*)d_in[13];
    const float* W2    = (const float*)d_in[14];
    const float* as2   = (const float*)d_in[15];
    const float* ad2   = (const float*)d_in[16];
    const float* bias2 = (const float*)d_in[17];
    float* out = (float*)d_out;

    float *hf1, *gat1, *hf2, *pas1, *pad1, *pas2, *pad2;
    cudaGetSymbolAddress((void**)&hf1,  g_hf1);
    cudaGetSymbolAddress((void**)&gat1, g_gat1);
    cudaGetSymbolAddress((void**)&hf2,  g_hf2);
    cudaGetSymbolAddress((void**)&pas1, g_pas1);
    cudaGetSymbolAddress((void**)&pad1, g_pad1);
    cudaGetSymbolAddress((void**)&pas2, g_pas2);
    cudaGetSymbolAddress((void**)&pad2, g_pad2);

    reset_flags<<<1, 256>>>();
    detect_dtype<<<1, 32>>>((const unsigned int*)eix);

    // CSR build (independent of GRU; quick)
    init_deg<<<(N_NODES + 255) / 256, 256>>>();
    count_deg<<<(N_EDGES + 255) / 256, 256>>>(eix);
    exscan_k<<<1, 1024>>>();
    fill_edges<<<(N_EDGES + 255) / 256, 256>>>(eix);
    fill_self<<<(N_NODES + 255) / 256, 256>>>();

    // pipelined GRU scans + streaming GEMMs + GAT1 feature transform
    mega<<<MEGA_BLOCKS, 384>>>(x, w_ih0, b_ih0, w_hh0, b_hh0,
                               w_ih1, b_ih1, w_hh1, b_hh1, W1, as1, ad1);

    // GAT layer 1 aggregation (+relu)
    gat_aggregate<HEADS1, HID, true><<<(N_NODES * 32 + 255) / 256, 256>>>(hf1, pas1, pad1, bias1, gat1);

    // GAT layer 2
    gemm_nn<<<(N_NODES * (OUTD / 4) + 255) / 256, 256>>>(gat1, W2, hf2, N_NODES, HC1, OUTD);
    att_dots<1, OUTD><<<(N_NODES + 255) / 256, 256>>>(hf2, as2, ad2, pas2, pad2);
    gat_aggregate<1, OUTD, false><<<(N_NODES * 32 + 255) / 256, 256>>>(hf2, pas2, pad2, bias2, out);
}

// round 3
// speedup vs baseline: 2.1914x; 1.1497x over previous
#include <cuda_runtime.h>

#define N_NODES 10000
#define N_EDGES 320000
#define IN_DIM  64
#define HID     128
#define G3      384
#define HEADS1  4
#define HC1     512
#define OUTD    64
#define TOT_E   (N_EDGES + N_NODES)

#define SL      64                        // rows per pipeline slice
#define NS      ((N_NODES + SL - 1) / SL) // 157 slices
#define GA      32
#define GB      32
#define GD      40
#define MEGA_BLOCKS (2 + GA + GB + GD)    // 106
#define PF      4                         // gi prefetch ring (steps)

typedef unsigned long long ull;

// ---------------- scratch ----------------
__device__ __align__(16) float g_gi0 [N_NODES * G3];
__device__ __align__(16) float g_gi1 [N_NODES * G3];
__device__ __align__(16) float g_h0  [N_NODES * HID];
__device__ __align__(16) float g_h1  [N_NODES * HID];
__device__ __align__(16) float g_hf1 [N_NODES * HC1];
__device__ __align__(16) float g_gat1[N_NODES * HC1];
__device__ __align__(16) float g_hf2 [N_NODES * OUTD];
__device__ float g_pas1[N_NODES * HEADS1];
__device__ float g_pad1[N_NODES * HEADS1];
__device__ float g_pas2[N_NODES];
__device__ float g_pad2[N_NODES];
__device__ int   g_deg [N_NODES];
__device__ int   g_off [N_NODES + 1];
__device__ int   g_cur [N_NODES];
__device__ int   g_adj [TOT_E];
__device__ int   g_is64;
// pipeline sync
__device__ int   g_f0[NS];
__device__ int   g_f1[NS];
__device__ int   g_h0done;
__device__ int   g_h1done;

__global__ void reset_flags() {
    int i = threadIdx.x;
    for (int s = i; s < NS; s += blockDim.x) { g_f0[s] = 0; g_f1[s] = 0; }
    if (i == 0) { g_h0done = 0; g_h1done = 0; }
}

// ---------------- helpers ----------------
__device__ __forceinline__ float sigmoidf_(float x) {
    return __fdividef(1.f, 1.f + __expf(-x));
}
__device__ __forceinline__ float tanhf_(float x) {
    return 1.f - __fdividef(2.f, __expf(2.f * x) + 1.f);
}
__device__ __forceinline__ ull packf2(float x, float y) {
    ull u; asm("mov.b64 %0, {%1, %2};" : "=l"(u) : "f"(x), "f"(y)); return u;
}
__device__ __forceinline__ void unpackf2(ull u, float& x, float& y) {
    asm("mov.b64 {%0, %1}, %2;" : "=f"(x), "=f"(y) : "l"(u));
}
__device__ __forceinline__ void wait_flag_acq(const int* p) {
    int f;
    do {
        asm volatile("ld.global.acquire.gpu.b32 %0, [%1];" : "=r"(f) : "l"(p));
        if (!f) __nanosleep(64);
    } while (!f);
}

// ---------------- edge dtype detection ----------------
__global__ void detect_dtype(const unsigned int* __restrict__ e) {
    if (threadIdx.x == 0 && blockIdx.x == 0) {
        int is64 = 1;
        for (int i = 1; i < 256; i += 2)
            if (e[i] != 0u) { is64 = 0; break; }
        g_is64 = is64;
    }
}
__device__ __forceinline__ int ld_edge(const void* e, int i) {
    if (g_is64) return (int)((const long long*)e)[i];
    return ((const int*)e)[i];
}

// =========================================================================
// MEGA KERNEL roles
// =========================================================================

// ---- GRU scan: 1 CTA, 384 threads; thread t owns row t of w_hh in regs ----
__device__ void scan_role(unsigned char* sraw,
                          const float* __restrict__ gi,
                          const float* __restrict__ w_hh,
                          const float* __restrict__ b_hh,
                          float* __restrict__ out,
                          const int* flags, int* prog) {
    ull*   hs   = (ull*)sraw;              // 64 f32x2
    float* sgh  = (float*)(sraw + 512);    // 384
    float* sgin = (float*)(sraw + 2048);   // 128
    const int t = threadIdx.x;

    ull w[64];
    const float2* wrow = reinterpret_cast<const float2*>(w_hh + t * 128);
#pragma unroll
    for (int k = 0; k < 64; ++k) { float2 v = wrow[k]; w[k] = packf2(v.x, v.y); }
    float bh = b_hh[t];
    if (t < 64) hs[t] = 0ull;

    // wait for slice 0 before prologue prefetch
    if (t == 0) wait_flag_acq(flags);
    __syncthreads();

    float ring[PF];
#pragma unroll
    for (int j = 0; j < PF; ++j) ring[j] = gi[j * G3 + t];

    int Rprev = 0;
    for (int sb = 0; sb < N_NODES; sb += PF) {
        // slices needed through step sb+PF-1 and prefetch up to sb+2*PF-1
        int R = (sb + 2 * PF - 1) >> 6;
        if (R > NS - 1) R = NS - 1;
        if (R != Rprev) {
            if (t == 0) wait_flag_acq(flags + R);
            Rprev = R;
            __syncthreads();
        }
#pragma unroll
        for (int j = 0; j < PF; ++j) {
            const int step = sb + j;
            float giv = ring[j];
            // prefetch step+PF into the slot just consumed
            int pstep = step + PF; if (pstep > N_NODES - 1) pstep = N_NODES - 1;
            ring[j] = gi[pstep * G3 + t];

            ull a0 = 0ull, a1 = 0ull, a2 = 0ull, a3 = 0ull;
#pragma unroll
            for (int k = 0; k < 64; k += 4) {
                ulonglong2 h01 = *reinterpret_cast<const ulonglong2*>(&hs[k]);
                ulonglong2 h23 = *reinterpret_cast<const ulonglong2*>(&hs[k + 2]);
                asm("fma.rn.f32x2 %0, %1, %2, %0;" : "+l"(a0) : "l"(w[k]),     "l"(h01.x));
                asm("fma.rn.f32x2 %0, %1, %2, %0;" : "+l"(a1) : "l"(w[k + 1]), "l"(h01.y));
                asm("fma.rn.f32x2 %0, %1, %2, %0;" : "+l"(a2) : "l"(w[k + 2]), "l"(h23.x));
                asm("fma.rn.f32x2 %0, %1, %2, %0;" : "+l"(a3) : "l"(w[k + 3]), "l"(h23.y));
            }
            asm("add.rn.f32x2 %0, %0, %1;" : "+l"(a0) : "l"(a1));
            asm("add.rn.f32x2 %0, %0, %1;" : "+l"(a2) : "l"(a3));
            asm("add.rn.f32x2 %0, %0, %1;" : "+l"(a0) : "l"(a2));
            float lo, hi; unpackf2(a0, lo, hi);
            float gh = lo + hi + bh;

            sgh[t] = (t < 256) ? (gh + giv) : gh;
            if (t >= 256) sgin[t - 256] = giv;
            __syncthreads();

            if (t < 128) {
                float r = sigmoidf_(sgh[t]);
                float z = sigmoidf_(sgh[t + 128]);
                float n = tanhf_(sgin[t] + r * sgh[t + 256]);
                float hold = reinterpret_cast<const float*>(hs)[t];
                float hnew = (1.f - z) * n + z * hold;
                reinterpret_cast<float*>(hs)[t] = hnew;
                out[step * HID + t] = hnew;
            }
            __syncthreads();
        }
        // publish progress every 32 steps (thread0-only fence)
        int done = sb + PF;
        if ((done & 31) == 0 || done == N_NODES) {
            if (t == 0) {
                asm volatile("fence.acq_rel.gpu;" ::: "memory");
                asm volatile("st.global.relaxed.gpu.b32 [%0], %1;" :: "l"(prog), "r"(done) : "memory");
            }
        }
    }
}

// ---- gi0 = x @ w_ih0^T + b_ih0 ----
__device__ void gemmA_role(unsigned char* sraw, int cta,
                           const float* __restrict__ x,
                           const float* __restrict__ w_ih,
                           const float* __restrict__ b_ih) {
    float* sx = (float*)sraw;
    const int t = threadIdx.x;
    float4 w[16];
    const float4* wr = reinterpret_cast<const float4*>(w_ih + t * IN_DIM);
#pragma unroll
    for (int i = 0; i < 16; ++i) w[i] = wr[i];
    float b = b_ih[t];

    for (int s = cta; s < NS; s += GA) {
        int r0 = s * SL, r1 = min(r0 + SL, N_NODES), nr = r1 - r0;
        for (int i = t; i < nr * IN_DIM; i += 384) sx[i] = x[r0 * IN_DIM + i];
        __syncthreads();
        for (int r = 0; r < nr; ++r) {
            const float4* hx = reinterpret_cast<const float4*>(sx + r * IN_DIM);
            float acc = b;
#pragma unroll
            for (int i = 0; i < 16; ++i) {
                float4 a = hx[i];
                acc += a.x * w[i].x + a.y * w[i].y + a.z * w[i].z + a.w * w[i].w;
            }
            g_gi0[(r0 + r) * G3 + t] = acc;
        }
        __threadfence();
        __syncthreads();
        if (t == 0) ((volatile int*)g_f0)[s] = 1;
        __syncthreads();
    }
}

// ---- gi1 = h0 @ w_ih1^T + b_ih1 : polls h0 progress ----
__device__ void gemmB_role(unsigned char* sraw, int cta,
                           const float* __restrict__ w_ih,
                           const float* __restrict__ b_ih) {
    ull* sh = (ull*)sraw;
    const int t = threadIdx.x;
    ull w[64];
    const float2* wr = reinterpret_cast<const float2*>(w_ih + t * HID);
#pragma unroll
    for (int k = 0; k < 64; ++k) { float2 v = wr[k]; w[k] = packf2(v.x, v.y); }
    float b = b_ih[t];

    for (int s = cta; s < NS; s += GB) {
        int r0 = s * SL, r1 = min(r0 + SL, N_NODES), nr = r1 - r0;
        if (t == 0) { while (*(volatile int*)&g_h0done < r1) __nanosleep(256); }
        __syncthreads();
        __threadfence();
        const ull* src = reinterpret_cast<const ull*>(g_h0 + r0 * HID);
        for (int i = t; i < nr * 64; i += 384) sh[i] = src[i];
        __syncthreads();
        for (int r = 0; r < nr; ++r) {
            const ull* hr = sh + r * 64;
            ull a0 = 0ull, a1 = 0ull;
#pragma unroll
            for (int k = 0; k < 64; k += 2) {
                asm("fma.rn.f32x2 %0, %1, %2, %0;" : "+l"(a0) : "l"(w[k]),     "l"(hr[k]));
                asm("fma.rn.f32x2 %0, %1, %2, %0;" : "+l"(a1) : "l"(w[k + 1]), "l"(hr[k + 1]));
            }
            asm("add.rn.f32x2 %0, %0, %1;" : "+l"(a0) : "l"(a1));
            float lo, hi; unpackf2(a0, lo, hi);
            g_gi1[(r0 + r) * G3 + t] = lo + hi + b;
        }
        __threadfence();
        __syncthreads();
        if (t == 0) ((volatile int*)g_f1)[s] = 1;
        __syncthreads();
    }
}

// ---- hf1 = h1 @ W1 (+ attention dots) : polls h1 progress ----
__device__ void gemmD_role(unsigned char* sraw, int cta,
                           const float* __restrict__ W1,
                           const float* __restrict__ as1,
                           const float* __restrict__ ad1) {
    ull* sh = (ull*)sraw;
    const int t = threadIdx.x;

    for (int s = cta; s < NS; s += GD) {
        int r0 = s * SL, r1 = min(r0 + SL, N_NODES), nr = r1 - r0;
        if (t == 0) { while (*(volatile int*)&g_h1done < r1) __nanosleep(256); }
        __syncthreads();
        __threadfence();
        const ull* src = reinterpret_cast<const ull*>(g_h1 + r0 * HID);
        for (int i = t; i < nr * 64; i += 384) sh[i] = src[i];
        __syncthreads();

        {
            int col = t;
            ull w[64];
#pragma unroll
            for (int k = 0; k < 64; ++k)
                w[k] = packf2(W1[(2 * k) * HC1 + col], W1[(2 * k + 1) * HC1 + col]);
            for (int r = 0; r < nr; ++r) {
                const ull* hr = sh + r * 64;
                ull a0 = 0ull, a1 = 0ull;
#pragma unroll
                for (int k = 0; k < 64; k += 2) {
                    asm("fma.rn.f32x2 %0, %1, %2, %0;" : "+l"(a0) : "l"(w[k]),     "l"(hr[k]));
                    asm("fma.rn.f32x2 %0, %1, %2, %0;" : "+l"(a1) : "l"(w[k + 1]), "l"(hr[k + 1]));
                }
                asm("add.rn.f32x2 %0, %0, %1;" : "+l"(a0) : "l"(a1));
                float lo, hi; unpackf2(a0, lo, hi);
                g_hf1[(long)(r0 + r) * HC1 + col] = lo + hi;
            }
        }
        if (t < 128) {
            int col = 384 + t;
            ull w[64];
#pragma unroll
            for (int k = 0; k < 64; ++k)
                w[k] = packf2(W1[(2 * k) * HC1 + col], W1[(2 * k + 1) * HC1 + col]);
            for (int r = 0; r < nr; ++r) {
                const ull* hr = sh + r * 64;
                ull a0 = 0ull, a1 = 0ull;
#pragma unroll
                for (int k = 0; k < 64; k += 2) {
                    asm("fma.rn.f32x2 %0, %1, %2, %0;" : "+l"(a0) : "l"(w[k]),     "l"(hr[k]));
                    asm("fma.rn.f32x2 %0, %1, %2, %0;" : "+l"(a1) : "l"(w[k + 1]), "l"(hr[k + 1]));
                }
                asm("add.rn.f32x2 %0, %0, %1;" : "+l"(a0) : "l"(a1));
                float lo, hi; unpackf2(a0, lo, hi);
                g_hf1[(long)(r0 + r) * HC1 + col] = lo + hi;
            }
        }
        __syncthreads();

        if (t < 256) {
            int row = t >> 2, h = t & 3;
            if (row < nr) {
                const float* v = g_hf1 + (long)(r0 + row) * HC1 + h * HID;
                float sa = 0.f, da = 0.f;
#pragma unroll 4
                for (int c = 0; c < HID; ++c) {
                    float xv = v[c];
                    sa += xv * as1[h * HID + c];
                    da += xv * ad1[h * HID + c];
                }
                g_pas1[(r0 + row) * HEADS1 + h] = sa;
                g_pad1[(r0 + row) * HEADS1 + h] = da;
            }
        }
        __syncthreads();
    }
}

__global__ void __launch_bounds__(384, 1)
mega(const float* __restrict__ x,
     const float* __restrict__ w_ih0, const float* __restrict__ b_ih0,
     const float* __restrict__ w_hh0, const float* __restrict__ b_hh0,
     const float* __restrict__ w_ih1, const float* __restrict__ b_ih1,
     const float* __restrict__ w_hh1, const float* __restrict__ b_hh1,
     const float* __restrict__ W1,
     const float* __restrict__ as1, const float* __restrict__ ad1) {
    __shared__ __align__(16) unsigned char sraw[64 * 64 * 8];
    int b = blockIdx.x;
    if (b == 0)
        scan_role(sraw, g_gi0, w_hh0, b_hh0, g_h0, g_f0, &g_h0done);
    else if (b == 1)
        scan_role(sraw, g_gi1, w_hh1, b_hh1, g_h1, g_f1, &g_h1done);
    else if (b < 2 + GA)
        gemmA_role(sraw, b - 2, x, w_ih0, b_ih0);
    else if (b < 2 + GA + GB)
        gemmB_role(sraw, b - 2 - GA, w_ih1, b_ih1);
    else
        gemmD_role(sraw, b - 2 - GA - GB, W1, as1, ad1);
}

// =========================================================================
// CSR build
// =========================================================================
__global__ void init_deg() {
    int n = blockIdx.x * blockDim.x + threadIdx.x;
    if (n < N_NODES) g_deg[n] = 1;
}
__global__ void count_deg(const void* e) {
    int i = blockIdx.x * blockDim.x + threadIdx.x;
    if (i < N_EDGES) atomicAdd(&g_deg[ld_edge(e, N_EDGES + i)], 1);
}
__global__ void exscan_k() {
    __shared__ int part[1024];
    const int CH = 10;
    int tid = threadIdx.x;
    int base = tid * CH;
    int s = 0;
    for (int i = 0; i < CH; ++i) { int idx = base + i; if (idx < N_NODES) s += g_deg[idx]; }
    part[tid] = s;
    __syncthreads();
    if (tid == 0) {
        int run = 0;
        for (int i = 0; i < 1024; ++i) { int v = part[i]; part[i] = run; run += v; }
        g_off[N_NODES] = run;
    }
    __syncthreads();
    int run = part[tid];
    for (int i = 0; i < CH; ++i) {
        int idx = base + i;
        if (idx < N_NODES) { g_off[idx] = run; g_cur[idx] = run; run += g_deg[idx]; }
    }
}
__global__ void fill_edges(const void* e) {
    int i = blockIdx.x * blockDim.x + threadIdx.x;
    if (i < N_EDGES) {
        int src = ld_edge(e, i);
        int dst = ld_edge(e, N_EDGES + i);
        g_adj[atomicAdd(&g_cur[dst], 1)] = src;
    }
}
__global__ void fill_self() {
    int n = blockIdx.x * blockDim.x + threadIdx.x;
    if (n < N_NODES) g_adj[atomicAdd(&g_cur[n], 1)] = n;
}

// =========================================================================
// tail kernels
// =========================================================================
template <int HEADS, int C>
__global__ void att_dots(const float* __restrict__ hf, const float* __restrict__ atts,
                         const float* __restrict__ attd,
                         float* __restrict__ a_s, float* __restrict__ a_d) {
    int idx = blockIdx.x * blockDim.x + threadIdx.x;
    if (idx >= N_NODES * HEADS) return;
    int n = idx / HEADS, h = idx - n * HEADS;
    const float* v = hf + (long)n * HEADS * C + h * C;
    float s = 0.f, d = 0.f;
#pragma unroll 4
    for (int c = 0; c < C; ++c) {
        float xv = v[c];
        s += xv * atts[h * C + c];
        d += xv * attd[h * C + c];
    }
    a_s[idx] = s;
    a_d[idx] = d;
}

template <int HEADS, int C, bool RELU>
__global__ void gat_aggregate(const float* __restrict__ hf, const float* __restrict__ a_s,
                              const float* __restrict__ a_d, const float* __restrict__ bias,
                              float* __restrict__ out) {
    constexpr int HC  = HEADS * C;
    constexpr int FPL = HC / 32;
    int warp = (blockIdx.x * blockDim.x + threadIdx.x) >> 5;
    int lane = threadIdx.x & 31;
    if (warp >= N_NODES) return;
    int s0 = g_off[warp], s1 = g_off[warp + 1];

    float ad[HEADS], m[HEADS], den[HEADS];
#pragma unroll
    for (int h = 0; h < HEADS; ++h) {
        ad[h] = a_d[warp * HEADS + h];
        m[h] = -1e30f;
        den[h] = 0.f;
    }
    for (int j = s0 + lane; j < s1; j += 32) {
        int src = g_adj[j];
#pragma unroll
        for (int h = 0; h < HEADS; ++h) {
            float e = a_s[src * HEADS + h] + ad[h];
            e = (e > 0.f) ? e : 0.2f * e;
            m[h] = fmaxf(m[h], e);
        }
    }
#pragma unroll
    for (int h = 0; h < HEADS; ++h)
        for (int o = 16; o > 0; o >>= 1)
            m[h] = fmaxf(m[h], __shfl_xor_sync(0xffffffffu, m[h], o));
    for (int j = s0 + lane; j < s1; j += 32) {
        int src = g_adj[j];
#pragma unroll
        for (int h = 0; h < HEADS; ++h) {
            float e = a_s[src * HEADS + h] + ad[h];
            e = (e > 0.f) ? e : 0.2f * e;
            den[h] += __expf(e - m[h]);
        }
    }
#pragma unroll
    for (int h = 0; h < HEADS; ++h) {
        for (int o = 16; o > 0; o >>= 1)
            den[h] += __shfl_xor_sync(0xffffffffu, den[h], o);
        den[h] = __fdividef(1.f, den[h]);
    }
    float acc[FPL];
#pragma unroll
    for (int f = 0; f < FPL; ++f) acc[f] = 0.f;
    for (int j = s0; j < s1; ++j) {
        int src = g_adj[j];
        float w[HEADS];
#pragma unroll
        for (int h = 0; h < HEADS; ++h) {
            float e = a_s[src * HEADS + h] + ad[h];
            e = (e > 0.f) ? e : 0.2f * e;
            w[h] = __expf(e - m[h]) * den[h];
        }
        const float* hrow = hf + (long)src * HC;
#pragma unroll
        for (int f = 0; f < FPL; ++f)
            acc[f] += w[(f * 32) / C] * hrow[lane + f * 32];
    }
#pragma unroll
    for (int f = 0; f < FPL; ++f) {
        int feat = lane + f * 32;
        float v = acc[f] + bias[feat];
        if (RELU) v = fmaxf(v, 0.f);
        out[(long)warp * HC + feat] = v;
    }
}

__global__ void gemm_nn(const float* __restrict__ A, const float* __restrict__ B,
                        float* __restrict__ out, int N, int K, int M) {
    int M4 = M >> 2;
    int idx = blockIdx.x * blockDim.x + threadIdx.x;
    if (idx >= N * M4) return;
    int n = idx / M4, m4 = idx - n * M4;
    const float* arow = A + (long)n * K;
    const float4* bp = reinterpret_cast<const float4*>(B) + m4;
    float4 acc = make_float4(0.f, 0.f, 0.f, 0.f);
    for (int k = 0; k < K; ++k) {
        float av = arow[k];
        float4 bv = bp[(long)k * M4];
        acc.x += av * bv.x; acc.y += av * bv.y;
        acc.z += av * bv.z; acc.w += av * bv.w;
    }
    reinterpret_cast<float4*>(out)[idx] = acc;
}

// =========================================================================
// launch
// =========================================================================
extern "C" void kernel_launch(void* const* d_in, const int* in_sizes, int n_in,
                              void* d_out, int out_size) {
    const float* x     = (const float*)d_in[0];
    const void*  eix   = d_in[1];
    const float* w_ih0 = (const float*)d_in[2];
    const float* w_hh0 = (const float*)d_in[3];
    const float* b_ih0 = (const float*)d_in[4];
    const float* b_hh0 = (const float*)d_in[5];
    const float* w_ih1 = (const float*)d_in[6];
    const float* w_hh1 = (const float*)d_in[7];
    const float* b_ih1 = (const float*)d_in[8];
    const float* b_hh1 = (const float*)d_in[9];
    const float* W1    = (const float*)d_in[10];
    const float* as1   = (const float*)d_in[11];
    const float* ad1   = (const float*)d_in[12];
    const float* bias1 = (const float*)d_in[13];
    const float* W2    = (const float*)d_in[14];
    const float* as2   = (const float*)d_in[15];
    const float* ad2   = (const float*)d_in[16];
    const float* bias2 = (const float*)d_in[17];
    float* out = (float*)d_out;

    float *hf1, *gat1, *hf2, *pas1, *pad1, *pas2, *pad2;
    cudaGetSymbolAddress((void**)&hf1,  g_hf1);
    cudaGetSymbolAddress((void**)&gat1, g_gat1);
    cudaGetSymbolAddress((void**)&hf2,  g_hf2);
    cudaGetSymbolAddress((void**)&pas1, g_pas1);
    cudaGetSymbolAddress((void**)&pad1, g_pad1);
    cudaGetSymbolAddress((void**)&pas2, g_pas2);
    cudaGetSymbolAddress((void**)&pad2, g_pad2);

    // launches 1-5 (so mega is the 6th launch, which ncu -s 5 -c 1 profiles)
    reset_flags<<<1, 256>>>();
    detect_dtype<<<1, 32>>>((const unsigned int*)eix);
    init_deg<<<(N_NODES + 255) / 256, 256>>>();
    count_deg<<<(N_EDGES + 255) / 256, 256>>>(eix);
    exscan_k<<<1, 1024>>>();

    // launch 6: pipelined GRU scans + streaming GEMMs + GAT1 features
    mega<<<MEGA_BLOCKS, 384>>>(x, w_ih0, b_ih0, w_hh0, b_hh0,
                               w_ih1, b_ih1, w_hh1, b_hh1, W1, as1, ad1);

    // CSR fill (only needed by gat_aggregate below)
    fill_edges<<<(N_EDGES + 255) / 256, 256>>>(eix);
    fill_self<<<(N_NODES + 255) / 256, 256>>>();

    // GAT layer 1 aggregation (+relu)
    gat_aggregate<HEADS1, HID, true><<<(N_NODES * 32 + 255) / 256, 256>>>(hf1, pas1, pad1, bias1, gat1);

    // GAT layer 2
    gemm_nn<<<(N_NODES * (OUTD / 4) + 255) / 256, 256>>>(gat1, W2, hf2, N_NODES, HC1, OUTD);
    att_dots<1, OUTD><<<(N_NODES + 255) / 256, 256>>>(hf2, as2, ad2, pas2, pad2);
    gat_aggregate<1, OUTD, false><<<(N_NODES * 32 + 255) / 256, 256>>>(hf2, pas2, pad2, bias2, out);
}